// round 1
// baseline (speedup 1.0000x reference)
#include <cuda_runtime.h>

// Problem constants
constexpr int B = 16, C = 64, H = 256, W = 256;
constexpr int PLANES = B * C;        // 1024
constexpr int PLANE_ELEMS = H * W;   // 65536

// Block: 64 threads in x (64 * float4 = 256 cols), 4 rows in y.
// Grid: (1, H/4 = 64, PLANES = 1024)
__global__ __launch_bounds__(256) void ParConv2d_kernel(
    const float* __restrict__ x,
    const float* __restrict__ kern,
    float* __restrict__ y)
{
    const int p   = blockIdx.z;          // plane = b*C + c
    const int b   = p >> 6;              // / C
    const int row = blockIdx.y * 4 + threadIdx.y;
    const int w0  = threadIdx.x << 2;    // aligned float4 start col

    // Per-batch 3x3 kernel (block-uniform loads -> L1 broadcast)
    const float* kb = kern + b * 9;
    const float k00 = __ldg(kb + 0), k01 = __ldg(kb + 1), k02 = __ldg(kb + 2);
    const float k10 = __ldg(kb + 3), k11 = __ldg(kb + 4), k12 = __ldg(kb + 5);
    const float k20 = __ldg(kb + 6), k21 = __ldg(kb + 7), k22 = __ldg(kb + 8);

    const float* plane  = x + (size_t)p * PLANE_ELEMS;
    float*       oplane = y + (size_t)p * PLANE_ELEMS;

    // For each of the 3 contributing rows: left halo, 4 center vals, right halo
    float l[3], a0[3], a1[3], a2[3], a3[3], r[3];

    #pragma unroll
    for (int i = 0; i < 3; ++i) {
        const int rr = row - 1 + i;
        if (rr < 0 || rr >= H) {
            l[i] = a0[i] = a1[i] = a2[i] = a3[i] = r[i] = 0.0f;
        } else {
            const float* rp = plane + rr * W + w0;
            const float4 v = *reinterpret_cast<const float4*>(rp);
            a0[i] = v.x; a1[i] = v.y; a2[i] = v.z; a3[i] = v.w;
            l[i] = (w0 == 0)      ? 0.0f : __ldg(rp - 1);
            r[i] = (w0 + 4 >= W)  ? 0.0f : __ldg(rp + 4);
        }
    }

    float4 o;
    // out col w0:   taps (w0-1, w0, w0+1) => (l, a0, a1)
    o.x = k00*l[0]  + k01*a0[0] + k02*a1[0]
        + k10*l[1]  + k11*a0[1] + k12*a1[1]
        + k20*l[2]  + k21*a0[2] + k22*a1[2];
    // out col w0+1: (a0, a1, a2)
    o.y = k00*a0[0] + k01*a1[0] + k02*a2[0]
        + k10*a0[1] + k11*a1[1] + k12*a2[1]
        + k20*a0[2] + k21*a1[2] + k22*a2[2];
    // out col w0+2: (a1, a2, a3)
    o.z = k00*a1[0] + k01*a2[0] + k02*a3[0]
        + k10*a1[1] + k11*a2[1] + k12*a3[1]
        + k20*a1[2] + k21*a2[2] + k22*a3[2];
    // out col w0+3: (a2, a3, r)
    o.w = k00*a2[0] + k01*a3[0] + k02*r[0]
        + k10*a2[1] + k11*a3[1] + k12*r[1]
        + k20*a2[2] + k21*a3[2] + k22*r[2];

    *reinterpret_cast<float4*>(oplane + row * W + w0) = o;
}

extern "C" void kernel_launch(void* const* d_in, const int* in_sizes, int n_in,
                              void* d_out, int out_size)
{
    const float* x    = (const float*)d_in[0];   // (B, C, H, W) fp32
    const float* kern = (const float*)d_in[1];   // (B, 3, 3) fp32
    float*       y    = (float*)d_out;

    dim3 block(64, 4, 1);                 // 256 threads
    dim3 grid(1, H / 4, PLANES);          // (1, 64, 1024)
    ParConv2d_kernel<<<grid, block>>>(x, kern, y);
}

// round 2
// speedup vs baseline: 1.0516x; 1.0516x over previous
#include <cuda_runtime.h>

constexpr int B = 16, C = 64, H = 256, W = 256;
constexpr int PLANES = B * C;        // 1024
constexpr int PLANE_ELEMS = H * W;   // 65536

// Block: 64 threads in x (64 * float4 = 256 cols), 4 in y; each thread does 2 rows.
// Grid: (1, H/8 = 32, PLANES = 1024)
__global__ __launch_bounds__(256) void ParConv2d_kernel(
    const float* __restrict__ x,
    const float* __restrict__ kern,
    float* __restrict__ y)
{
    const int p    = blockIdx.z;            // plane = b*C + c
    const int b    = p >> 6;                // / C
    const int row  = blockIdx.y * 8 + threadIdx.y * 2;  // this thread: rows row, row+1
    const int w0   = threadIdx.x << 2;      // aligned float4 start col
    const int lane = threadIdx.x & 31;      // warp = 32 consecutive x, same y

    const float* kb = kern + b * 9;
    const float k00 = kb[0], k01 = kb[1], k02 = kb[2];
    const float k10 = kb[3], k11 = kb[4], k12 = kb[5];
    const float k20 = kb[6], k21 = kb[7], k22 = kb[8];

    const float* plane  = x + (size_t)p * PLANE_ELEMS;
    float*       oplane = y + (size_t)p * PLANE_ELEMS;

    // 4 input rows feed 2 output rows. For each input row keep:
    // l (col w0-1), a0..a3 (cols w0..w0+3), r (col w0+4)
    float l[4], a0[4], a1[4], a2[4], a3[4], r[4];

    #pragma unroll
    for (int i = 0; i < 4; ++i) {
        const int rr = row - 1 + i;               // uniform across the warp
        if (rr < 0 || rr >= H) {
            l[i] = a0[i] = a1[i] = a2[i] = a3[i] = r[i] = 0.0f;
        } else {
            const float* rp = plane + rr * W + w0;
            const float4 v = *reinterpret_cast<const float4*>(rp);
            float lv = __shfl_up_sync(0xffffffffu, v.w, 1);
            float rv = __shfl_down_sync(0xffffffffu, v.x, 1);
            if (lane == 0)  lv = (w0 == 0)     ? 0.0f : __ldg(rp - 1);
            if (lane == 31) rv = (w0 + 4 >= W) ? 0.0f : __ldg(rp + 4);
            a0[i] = v.x; a1[i] = v.y; a2[i] = v.z; a3[i] = v.w;
            l[i] = lv; r[i] = rv;
        }
    }

    // Output row `row` uses input rows 0,1,2; row+1 uses 1,2,3.
    #pragma unroll
    for (int orow = 0; orow < 2; ++orow) {
        const int i0 = orow, i1 = orow + 1, i2 = orow + 2;
        float4 o;
        o.x = k00*l[i0]  + k01*a0[i0] + k02*a1[i0]
            + k10*l[i1]  + k11*a0[i1] + k12*a1[i1]
            + k20*l[i2]  + k21*a0[i2] + k22*a1[i2];
        o.y = k00*a0[i0] + k01*a1[i0] + k02*a2[i0]
            + k10*a0[i1] + k11*a1[i1] + k12*a2[i1]
            + k20*a0[i2] + k21*a1[i2] + k22*a2[i2];
        o.z = k00*a1[i0] + k01*a2[i0] + k02*a3[i0]
            + k10*a1[i1] + k11*a2[i1] + k12*a3[i1]
            + k20*a1[i2] + k21*a2[i2] + k22*a3[i2];
        o.w = k00*a2[i0] + k01*a3[i0] + k02*r[i0]
            + k10*a2[i1] + k11*a3[i1] + k12*r[i1]
            + k20*a2[i2] + k21*a3[i2] + k22*r[i2];
        *reinterpret_cast<float4*>(oplane + (row + orow) * W + w0) = o;
    }
}

extern "C" void kernel_launch(void* const* d_in, const int* in_sizes, int n_in,
                              void* d_out, int out_size)
{
    const float* x    = (const float*)d_in[0];   // (B, C, H, W) fp32
    const float* kern = (const float*)d_in[1];   // (B, 3, 3) fp32
    float*       y    = (float*)d_out;

    dim3 block(64, 4, 1);                 // 256 threads
    dim3 grid(1, H / 8, PLANES);          // (1, 32, 1024)
    ParConv2d_kernel<<<grid, block>>>(x, kern, y);
}

// round 3
// speedup vs baseline: 1.2930x; 1.2295x over previous
#include <cuda_runtime.h>

constexpr int B = 16, C = 64, H = 256, W = 256;
constexpr int PLANES = B * C;        // 1024
constexpr int PLANE_ELEMS = H * W;   // 65536
constexpr int RPT = 4;               // output rows per thread

struct RowT { float4 a, b; float l, r; };   // cols w0-1 .. w0+8 (10 vals)

__device__ __forceinline__ RowT load_row(const float* __restrict__ plane,
                                         int rr, int w0, int lane)
{
    RowT t;
    if (rr < 0 || rr >= H) {
        t.a = make_float4(0.f, 0.f, 0.f, 0.f);
        t.b = t.a; t.l = 0.f; t.r = 0.f;
        return t;
    }
    const float* rp = plane + rr * W + w0;
    t.a = *reinterpret_cast<const float4*>(rp);
    t.b = *reinterpret_cast<const float4*>(rp + 4);
    // Warp spans the full row: lane 0's left halo and lane 31's right halo
    // are the zero padding — no loads needed.
    float lv = __shfl_up_sync(0xffffffffu, t.b.w, 1);
    float rv = __shfl_down_sync(0xffffffffu, t.a.x, 1);
    t.l = (lane == 0)  ? 0.f : lv;
    t.r = (lane == 31) ? 0.f : rv;
    return t;
}

__device__ __forceinline__ void acc_row(float o[8], const RowT& t,
                                        float k0, float k1, float k2)
{
    const float v0 = t.l,   v1 = t.a.x, v2 = t.a.y, v3 = t.a.z, v4 = t.a.w;
    const float v5 = t.b.x, v6 = t.b.y, v7 = t.b.z, v8 = t.b.w, v9 = t.r;
    o[0] += k0*v0 + k1*v1 + k2*v2;
    o[1] += k0*v1 + k1*v2 + k2*v3;
    o[2] += k0*v2 + k1*v3 + k2*v4;
    o[3] += k0*v3 + k1*v4 + k2*v5;
    o[4] += k0*v4 + k1*v5 + k2*v6;
    o[5] += k0*v5 + k1*v6 + k2*v7;
    o[6] += k0*v6 + k1*v7 + k2*v8;
    o[7] += k0*v7 + k1*v8 + k2*v9;
}

// Block (32, 8): one warp per y-slice, warp covers full 256-col row.
// Each thread: 8 cols x RPT rows. Block covers 8*RPT = 32 rows.
// Grid: (1, H/32 = 8, PLANES = 1024)
__global__ __launch_bounds__(256, 4) void ParConv2d_kernel(
    const float* __restrict__ x,
    const float* __restrict__ kern,
    float* __restrict__ y)
{
    const int p    = blockIdx.z;
    const int b    = p >> 6;
    const int lane = threadIdx.x;            // 0..31
    const int w0   = lane << 3;              // 8 cols per thread
    const int row0 = blockIdx.y * (8 * RPT) + threadIdx.y * RPT;

    const float* kb = kern + b * 9;
    const float k00 = kb[0], k01 = kb[1], k02 = kb[2];
    const float k10 = kb[3], k11 = kb[4], k12 = kb[5];
    const float k20 = kb[6], k21 = kb[7], k22 = kb[8];

    const float* plane  = x + (size_t)p * PLANE_ELEMS;
    float*       oplane = y + (size_t)p * PLANE_ELEMS;

    RowT r0 = load_row(plane, row0 - 1, w0, lane);
    RowT r1 = load_row(plane, row0,     w0, lane);

    #pragma unroll
    for (int i = 0; i < RPT; ++i) {
        RowT r2 = load_row(plane, row0 + 1 + i, w0, lane);

        float o[8] = {0.f, 0.f, 0.f, 0.f, 0.f, 0.f, 0.f, 0.f};
        acc_row(o, r0, k00, k01, k02);
        acc_row(o, r1, k10, k11, k12);
        acc_row(o, r2, k20, k21, k22);

        float* op = oplane + (row0 + i) * W + w0;
        *reinterpret_cast<float4*>(op)     = make_float4(o[0], o[1], o[2], o[3]);
        *reinterpret_cast<float4*>(op + 4) = make_float4(o[4], o[5], o[6], o[7]);

        r0 = r1; r1 = r2;
    }
}

extern "C" void kernel_launch(void* const* d_in, const int* in_sizes, int n_in,
                              void* d_out, int out_size)
{
    const float* x    = (const float*)d_in[0];   // (B, C, H, W) fp32
    const float* kern = (const float*)d_in[1];   // (B, 3, 3) fp32
    float*       y    = (float*)d_out;

    dim3 block(32, 8, 1);                   // 256 threads
    dim3 grid(1, H / (8 * RPT), PLANES);    // (1, 8, 1024)
    ParConv2d_kernel<<<grid, block>>>(x, kern, y);
}